// round 12
// baseline (speedup 1.0000x reference)
#include <cuda_runtime.h>

// Shapes (fixed for this problem)
#define BB   8
#define LL   200
#define HIDD 256
#define NH   8
#define DHH  32
#define NEGV (-4294967295.0f)   // -2^32 + 1, matches reference padding value

// Scratch (device globals: allocation-free rule)
__device__ float g_Qp[BB * LL * HIDD];
__device__ float g_Ks[BB * LL * HIDD];   // K-proj + abs_pos_K  (folded)
__device__ float g_Vs[BB * LL * HIDD];   // V-proj + abs_pos_V  (folded)

// ---------------------------------------------------------------------------
// Projection GEMM:  Y = X @ W^T + bias (+ optional abs_pos fold)
// M=1600, N=256, K=256.  grid (25, 4, 3): z selects Q/K/V. block = 256 thr.
// BM=BN=64, BK=32. 4x4 register micro-tile.
// ---------------------------------------------------------------------------
__global__ __launch_bounds__(256) void proj_kernel(
    const float* __restrict__ queries, const float* __restrict__ keys,
    const float* __restrict__ Wq, const float* __restrict__ bq,
    const float* __restrict__ Wk, const float* __restrict__ bk,
    const float* __restrict__ Wv, const float* __restrict__ bv,
    const float* __restrict__ apK, const float* __restrict__ apV)
{
    const int which = blockIdx.z;
    const float* X    = (which == 0) ? queries : keys;
    const float* W    = (which == 0) ? Wq : (which == 1) ? Wk : Wv;
    const float* bias = (which == 0) ? bq : (which == 1) ? bk : bv;
    const float* fold = (which == 0) ? (const float*)0 : (which == 1) ? apK : apV;
    float* Y          = (which == 0) ? g_Qp : (which == 1) ? g_Ks : g_Vs;

    __shared__ float As[32][65];   // [k][m], padded
    __shared__ float Bs[32][65];   // [k][n], padded

    const int tid = threadIdx.x;
    const int tx = tid & 15, ty = tid >> 4;
    const int row0 = blockIdx.x * 64, col0 = blockIdx.y * 64;

    const int lr  = tid >> 2;          // 0..63 (tile row to load)
    const int lc8 = (tid & 3) * 8;     // 0,8,16,24 (k-offset)

    float acc[4][4] = {};

    for (int kt = 0; kt < HIDD; kt += 32) {
        float4 av0 = *(const float4*)&X[(row0 + lr) * HIDD + kt + lc8];
        float4 av1 = *(const float4*)&X[(row0 + lr) * HIDD + kt + lc8 + 4];
        float4 bw0 = *(const float4*)&W[(col0 + lr) * HIDD + kt + lc8];
        float4 bw1 = *(const float4*)&W[(col0 + lr) * HIDD + kt + lc8 + 4];
        As[lc8 + 0][lr] = av0.x;  As[lc8 + 1][lr] = av0.y;
        As[lc8 + 2][lr] = av0.z;  As[lc8 + 3][lr] = av0.w;
        As[lc8 + 4][lr] = av1.x;  As[lc8 + 5][lr] = av1.y;
        As[lc8 + 6][lr] = av1.z;  As[lc8 + 7][lr] = av1.w;
        Bs[lc8 + 0][lr] = bw0.x;  Bs[lc8 + 1][lr] = bw0.y;
        Bs[lc8 + 2][lr] = bw0.z;  Bs[lc8 + 3][lr] = bw0.w;
        Bs[lc8 + 4][lr] = bw1.x;  Bs[lc8 + 5][lr] = bw1.y;
        Bs[lc8 + 6][lr] = bw1.z;  Bs[lc8 + 7][lr] = bw1.w;
        __syncthreads();
        #pragma unroll
        for (int kk = 0; kk < 32; kk++) {
            float a[4], b[4];
            #pragma unroll
            for (int i = 0; i < 4; i++) a[i] = As[kk][ty * 4 + i];
            #pragma unroll
            for (int j = 0; j < 4; j++) b[j] = Bs[kk][tx * 4 + j];
            #pragma unroll
            for (int i = 0; i < 4; i++)
                #pragma unroll
                for (int j = 0; j < 4; j++)
                    acc[i][j] += a[i] * b[j];
        }
        __syncthreads();
    }

    #pragma unroll
    for (int i = 0; i < 4; i++) {
        const int r = row0 + ty * 4 + i;
        #pragma unroll
        for (int j = 0; j < 4; j++) {
            const int cc = col0 + tx * 4 + j;
            float v = acc[i][j] + bias[cc];
            if (fold) v += fold[r * HIDD + cc];
            Y[r * HIDD + cc] = v;
        }
    }
}

// ---------------------------------------------------------------------------
// Attention: one CTA per (q, b); q remapped heaviest-first. 256 threads.
// Warp 0 compacts unmasked k's into klist (ballot scan) WHILE warps 1-7
// prefill logits with NEGV. All k-loop loads are unconditional.
// Phase 1: warp w handles klist[w + 8i]; lane holds 8 consecutive channels
//   (2 adjacent float4s, fully coalesced). Head h lives in lanes [4h,4h+4):
//   reduction = 2 shuffles (single chain), writer lane (l&3)==0.
// Phase 2: per-head softmax (warp w = head w).
// Phase 3: thread owns float4 channel group j, compact k strided mod 4;
//   identity-list fallback when every k is masked (uniform softmax case).
// ---------------------------------------------------------------------------
__global__ __launch_bounds__(256) void attn_kernel(
    const float* __restrict__ tmK, const float* __restrict__ tmV,
    const int* __restrict__ time_mask, const int* __restrict__ attn_mask,
    float* __restrict__ out)
{
    const int q = (LL - 1) - blockIdx.x;   // heaviest (largest k-range) first
    const int b = blockIdx.y;
    const int tid = threadIdx.x;
    const int w = tid >> 5;        // warp
    const int l = tid & 31;        // lane

    __shared__ float aw[NH][LL];
    __shared__ int   klist[LL];
    __shared__ int   s_nk;
    __shared__ float4 red[4][64];

    if (w == 0) {
        // Warp 0: compact unmasked k indices (order-preserving ballot scan)
        const int tmw = time_mask[b * LL + q];
        int base = 0;
        #pragma unroll
        for (int c0 = 0; c0 < 224; c0 += 32) {
            const int k = c0 + l;
            const bool un = (k < LL) && (tmw == 0) && (attn_mask[q * LL + k] == 0);
            const unsigned bal = __ballot_sync(0xffffffffu, un);
            if (un) klist[base + __popc(bal & ((1u << l) - 1u))] = k;
            base += __popc(bal);
        }
        if (l == 0) s_nk = base;
    } else {
        // Warps 1-7: prefill logits with the masked value
        for (int idx = tid - 32; idx < NH * LL; idx += 224)
            (&aw[0][0])[idx] = NEGV;
    }
    __syncthreads();
    const int nk = s_nk;

    const int ch0 = 8 * l;                 // this lane's 8-channel segment
    const float* __restrict__ Qp = g_Qp + (size_t)(b * LL + q) * HIDD;
    const float4 q0 = *(const float4*)(Qp + ch0);
    const float4 q1 = *(const float4*)(Qp + ch0 + 4);

    const float* __restrict__ Ks  = g_Ks + (size_t)(b * LL) * HIDD;
    const float* __restrict__ TMK = tmK + (size_t)(b * LL + q) * LL * HIDD;
    const float  scale = 0.17677669529663687f;   // 1/sqrt(32)

    const int  head = l >> 2;              // head owned by this 4-lane segment
    const bool wr   = (l & 3) == 0;

    // ---- Phase 1: logits over compacted k's ----
    #pragma unroll 2
    for (int i = w; i < nk; i += 8) {
        const int k = klist[i];
        const float4 a0 = *(const float4*)(Ks + k * HIDD + ch0);
        const float4 a1 = *(const float4*)(Ks + k * HIDD + ch0 + 4);
        const float4 t0 = __ldcs((const float4*)(TMK + (size_t)k * HIDD + ch0));
        const float4 t1 = __ldcs((const float4*)(TMK + (size_t)k * HIDD + ch0 + 4));
        float p = q0.x * (a0.x + t0.x) + q0.y * (a0.y + t0.y)
                + q0.z * (a0.z + t0.z) + q0.w * (a0.w + t0.w)
                + q1.x * (a1.x + t1.x) + q1.y * (a1.y + t1.y)
                + q1.z * (a1.z + t1.z) + q1.w * (a1.w + t1.w);
        p += __shfl_xor_sync(0xffffffffu, p, 1);
        p += __shfl_xor_sync(0xffffffffu, p, 2);
        if (wr) aw[head][k] = p * scale;
    }
    __syncthreads();

    // ---- Phase 2: per-head softmax (warp w = head w) ----
    {
        float vals[7];
        float mx = -3.402823466e38f;
        #pragma unroll
        for (int i = 0; i < 7; i++) {
            const int k = l + 32 * i;
            float v = (k < LL) ? aw[w][k] : -3.402823466e38f;
            vals[i] = v;
            mx = fmaxf(mx, v);
        }
        #pragma unroll
        for (int o = 16; o > 0; o >>= 1)
            mx = fmaxf(mx, __shfl_xor_sync(0xffffffffu, mx, o));
        float s = 0.f;
        #pragma unroll
        for (int i = 0; i < 7; i++) {
            const int k = l + 32 * i;
            if (k < LL) { vals[i] = __expf(vals[i] - mx); s += vals[i]; }
        }
        #pragma unroll
        for (int o = 16; o > 0; o >>= 1)
            s += __shfl_xor_sync(0xffffffffu, s, o);
        const float inv = 1.0f / s;
        #pragma unroll
        for (int i = 0; i < 7; i++) {
            const int k = l + 32 * i;
            if (k < LL) aw[w][k] = vals[i] * inv;
        }
    }
    __syncthreads();

    // Degenerate fully-masked row: softmax is uniform over ALL k -> phase 3
    // must visit every k. Swap in an identity list. (Block-uniform branch.)
    int nk3 = nk;
    if (nk3 == 0) {
        for (int i = tid; i < LL; i += 256) klist[i] = i;
        nk3 = LL;
        __syncthreads();
    }

    // ---- Phase 3: weighted value accumulation (float4 per thread) ----
    const int j  = tid & 63;       // channel group: channels [4j, 4j+4)
    const int kq = tid >> 6;       // k offset mod 4 (uniform per warp)
    const int h3 = j >> 3;         // head of channels 4j..4j+3
    const float* __restrict__ Vs  = g_Vs + (size_t)(b * LL) * HIDD;
    const float* __restrict__ TMV = tmV + (size_t)(b * LL + q) * LL * HIDD;

    float4 acc = make_float4(0.f, 0.f, 0.f, 0.f);
    #pragma unroll 4
    for (int i = kq; i < nk3; i += 4) {
        const int k = klist[i];
        const float wgt = aw[h3][k];
        const float4 v = *(const float4*)(Vs + k * HIDD + 4 * j);
        const float4 t = __ldcs((const float4*)(TMV + (size_t)k * HIDD + 4 * j));
        acc.x += wgt * (v.x + t.x);
        acc.y += wgt * (v.y + t.y);
        acc.z += wgt * (v.z + t.z);
        acc.w += wgt * (v.w + t.w);
    }
    red[kq][j] = acc;
    __syncthreads();
    if (kq == 0) {
        const float4 r1 = red[1][j], r2 = red[2][j], r3 = red[3][j];
        acc.x += r1.x + r2.x + r3.x;
        acc.y += r1.y + r2.y + r3.y;
        acc.z += r1.z + r2.z + r3.z;
        acc.w += r1.w + r2.w + r3.w;
        *(float4*)(out + (size_t)(b * LL + q) * HIDD + 4 * j) = acc;
    }
}

// ---------------------------------------------------------------------------
extern "C" void kernel_launch(void* const* d_in, const int* in_sizes, int n_in,
                              void* d_out, int out_size)
{
    const float* queries   = (const float*)d_in[0];
    const float* keys      = (const float*)d_in[1];
    const int*   time_mask = (const int*)  d_in[2];
    const int*   attn_mask = (const int*)  d_in[3];
    const float* tmK       = (const float*)d_in[4];
    const float* tmV       = (const float*)d_in[5];
    const float* apK       = (const float*)d_in[6];
    const float* apV       = (const float*)d_in[7];
    // d_in[8] = time_attn (unused by the forward pass)
    const float* Wq        = (const float*)d_in[9];
    const float* bq        = (const float*)d_in[10];
    const float* Wk        = (const float*)d_in[11];
    const float* bk        = (const float*)d_in[12];
    const float* Wv        = (const float*)d_in[13];
    const float* bv        = (const float*)d_in[14];
    float* out = (float*)d_out;

    dim3 pgrid(1600 / 64, HIDD / 64, 3);   // (25, 4, 3)
    proj_kernel<<<pgrid, 256>>>(queries, keys, Wq, bq, Wk, bk, Wv, bv, apK, apV);

    dim3 agrid(LL, BB);                     // (200, 8)
    attn_kernel<<<agrid, 256>>>(tmK, tmV, time_mask, attn_mask, out);
}

// round 13
// speedup vs baseline: 1.0054x; 1.0054x over previous
#include <cuda_runtime.h>

// Shapes (fixed for this problem)
#define BB   8
#define LL   200
#define HIDD 256
#define NH   8
#define DHH  32
#define NEGV (-4294967295.0f)   // -2^32 + 1, matches reference padding value

// Scratch (device globals: allocation-free rule)
__device__ float g_Qp[BB * LL * HIDD];
__device__ float g_Ks[BB * LL * HIDD];   // K-proj + abs_pos_K  (folded)
__device__ float g_Vs[BB * LL * HIDD];   // V-proj + abs_pos_V  (folded)

// ---------------------------------------------------------------------------
// Projection GEMM:  Y = X @ W^T + bias (+ optional abs_pos fold)
// M=1600, N=256, K=256.  grid (25, 4, 3): z selects Q/K/V. block = 256 thr.
// BM=BN=64, BK=32. 4x4 register micro-tile.
// ---------------------------------------------------------------------------
__global__ __launch_bounds__(256) void proj_kernel(
    const float* __restrict__ queries, const float* __restrict__ keys,
    const float* __restrict__ Wq, const float* __restrict__ bq,
    const float* __restrict__ Wk, const float* __restrict__ bk,
    const float* __restrict__ Wv, const float* __restrict__ bv,
    const float* __restrict__ apK, const float* __restrict__ apV)
{
    const int which = blockIdx.z;
    const float* X    = (which == 0) ? queries : keys;
    const float* W    = (which == 0) ? Wq : (which == 1) ? Wk : Wv;
    const float* bias = (which == 0) ? bq : (which == 1) ? bk : bv;
    const float* fold = (which == 0) ? (const float*)0 : (which == 1) ? apK : apV;
    float* Y          = (which == 0) ? g_Qp : (which == 1) ? g_Ks : g_Vs;

    __shared__ float As[32][65];   // [k][m], padded
    __shared__ float Bs[32][65];   // [k][n], padded

    const int tid = threadIdx.x;
    const int tx = tid & 15, ty = tid >> 4;
    const int row0 = blockIdx.x * 64, col0 = blockIdx.y * 64;

    const int lr  = tid >> 2;          // 0..63 (tile row to load)
    const int lc8 = (tid & 3) * 8;     // 0,8,16,24 (k-offset)

    float acc[4][4] = {};

    for (int kt = 0; kt < HIDD; kt += 32) {
        float4 av0 = *(const float4*)&X[(row0 + lr) * HIDD + kt + lc8];
        float4 av1 = *(const float4*)&X[(row0 + lr) * HIDD + kt + lc8 + 4];
        float4 bw0 = *(const float4*)&W[(col0 + lr) * HIDD + kt + lc8];
        float4 bw1 = *(const float4*)&W[(col0 + lr) * HIDD + kt + lc8 + 4];
        As[lc8 + 0][lr] = av0.x;  As[lc8 + 1][lr] = av0.y;
        As[lc8 + 2][lr] = av0.z;  As[lc8 + 3][lr] = av0.w;
        As[lc8 + 4][lr] = av1.x;  As[lc8 + 5][lr] = av1.y;
        As[lc8 + 6][lr] = av1.z;  As[lc8 + 7][lr] = av1.w;
        Bs[lc8 + 0][lr] = bw0.x;  Bs[lc8 + 1][lr] = bw0.y;
        Bs[lc8 + 2][lr] = bw0.z;  Bs[lc8 + 3][lr] = bw0.w;
        Bs[lc8 + 4][lr] = bw1.x;  Bs[lc8 + 5][lr] = bw1.y;
        Bs[lc8 + 6][lr] = bw1.z;  Bs[lc8 + 7][lr] = bw1.w;
        __syncthreads();
        #pragma unroll
        for (int kk = 0; kk < 32; kk++) {
            float a[4], b[4];
            #pragma unroll
            for (int i = 0; i < 4; i++) a[i] = As[kk][ty * 4 + i];
            #pragma unroll
            for (int j = 0; j < 4; j++) b[j] = Bs[kk][tx * 4 + j];
            #pragma unroll
            for (int i = 0; i < 4; i++)
                #pragma unroll
                for (int j = 0; j < 4; j++)
                    acc[i][j] += a[i] * b[j];
        }
        __syncthreads();
    }

    #pragma unroll
    for (int i = 0; i < 4; i++) {
        const int r = row0 + ty * 4 + i;
        #pragma unroll
        for (int j = 0; j < 4; j++) {
            const int cc = col0 + tx * 4 + j;
            float v = acc[i][j] + bias[cc];
            if (fold) v += fold[r * HIDD + cc];
            Y[r * HIDD + cc] = v;
        }
    }
}

// ---------------------------------------------------------------------------
// Attention: one CTA per (q, b); q remapped heaviest-first. 256 threads.
// Warp 0 compacts unmasked k's (ballot scan) while warps 1-7 prefill NEGV.
// Contiguity fast-path: when the unmasked set is a contiguous range
// [k0, k0+nk) (detected from the compaction, data-driven), hot loops index
// k = k0 + i directly -> no smem in the address path, affine addresses,
// deeper unroll. Generic klist fallback otherwise. Fully-masked row ->
// contiguous [0, LL) with uniform softmax weights (matches reference).
// Phase 1 (R11 lane layout): lane holds channels 4l..4l+4 and 128+4l..;
//   segmented 8-lane reduction gives all 8 heads per k.
// ---------------------------------------------------------------------------
__global__ __launch_bounds__(256) void attn_kernel(
    const float* __restrict__ tmK, const float* __restrict__ tmV,
    const int* __restrict__ time_mask, const int* __restrict__ attn_mask,
    float* __restrict__ out)
{
    const int q = (LL - 1) - blockIdx.x;   // heaviest (largest k-range) first
    const int b = blockIdx.y;
    const int tid = threadIdx.x;
    const int w = tid >> 5;        // warp
    const int l = tid & 31;        // lane

    __shared__ float aw[NH][LL];
    __shared__ int   klist[LL];
    __shared__ int   s_nk, s_k0, s_contig;
    __shared__ float4 red[4][64];

    if (w == 0) {
        // Warp 0: compact unmasked k indices (order-preserving ballot scan)
        const int tmw = time_mask[b * LL + q];
        int base = 0;
        #pragma unroll
        for (int c0 = 0; c0 < 224; c0 += 32) {
            const int k = c0 + l;
            const bool un = (k < LL) && (tmw == 0) && (attn_mask[q * LL + k] == 0);
            const unsigned bal = __ballot_sync(0xffffffffu, un);
            if (un) klist[base + __popc(bal & ((1u << l) - 1u))] = k;
            base += __popc(bal);
        }
        if (l == 0) {
            s_nk = base;
            if (base > 0) {
                const int k0 = klist[0];
                s_k0 = k0;
                s_contig = (klist[base - 1] - k0 == base - 1);
            } else {
                s_k0 = 0;
                s_contig = 1;
            }
        }
    } else {
        // Warps 1-7: prefill logits with the masked value
        for (int idx = tid - 32; idx < NH * LL; idx += 224)
            (&aw[0][0])[idx] = NEGV;
    }
    __syncthreads();
    const int nk     = s_nk;
    const int k0     = s_k0;
    const int contig = s_contig;

    const float* __restrict__ Qp = g_Qp + (size_t)(b * LL + q) * HIDD;
    const float4 q0 = *(const float4*)(Qp + 4 * l);
    const float4 q1 = *(const float4*)(Qp + 128 + 4 * l);

    const float* __restrict__ Ks  = g_Ks + (size_t)(b * LL) * HIDD;
    const float* __restrict__ TMK = tmK + (size_t)(b * LL + q) * LL * HIDD;
    const float  scale = 0.17677669529663687f;   // 1/sqrt(32)

    const int  seg = l >> 3;           // 0..3: p0 -> head seg, p1 -> head 4+seg
    const bool wr  = (l & 7) == 0;

    // ---- Phase 1: logits ----
    if (contig) {
        const float* __restrict__ pK = Ks  + (size_t)k0 * HIDD + 4 * l;
        const float* __restrict__ pT = TMK + (size_t)k0 * HIDD + 4 * l;
        #pragma unroll 4
        for (int i = w; i < nk; i += 8) {
            const int k = k0 + i;
            const float4 a0 = *(const float4*)(pK + (size_t)i * HIDD);
            const float4 a1 = *(const float4*)(pK + (size_t)i * HIDD + 128);
            const float4 t0 = __ldcs((const float4*)(pT + (size_t)i * HIDD));
            const float4 t1 = __ldcs((const float4*)(pT + (size_t)i * HIDD + 128));
            float p0 = q0.x * (a0.x + t0.x) + q0.y * (a0.y + t0.y)
                     + q0.z * (a0.z + t0.z) + q0.w * (a0.w + t0.w);
            float p1 = q1.x * (a1.x + t1.x) + q1.y * (a1.y + t1.y)
                     + q1.z * (a1.z + t1.z) + q1.w * (a1.w + t1.w);
            p0 += __shfl_xor_sync(0xffffffffu, p0, 1);
            p0 += __shfl_xor_sync(0xffffffffu, p0, 2);
            p0 += __shfl_xor_sync(0xffffffffu, p0, 4);
            p1 += __shfl_xor_sync(0xffffffffu, p1, 1);
            p1 += __shfl_xor_sync(0xffffffffu, p1, 2);
            p1 += __shfl_xor_sync(0xffffffffu, p1, 4);
            if (wr) { aw[seg][k] = p0 * scale; aw[4 + seg][k] = p1 * scale; }
        }
    } else {
        #pragma unroll 2
        for (int i = w; i < nk; i += 8) {
            const int k = klist[i];
            const float4 a0 = *(const float4*)(Ks + k * HIDD + 4 * l);
            const float4 a1 = *(const float4*)(Ks + k * HIDD + 128 + 4 * l);
            const float4 t0 = __ldcs((const float4*)(TMK + (size_t)k * HIDD + 4 * l));
            const float4 t1 = __ldcs((const float4*)(TMK + (size_t)k * HIDD + 128 + 4 * l));
            float p0 = q0.x * (a0.x + t0.x) + q0.y * (a0.y + t0.y)
                     + q0.z * (a0.z + t0.z) + q0.w * (a0.w + t0.w);
            float p1 = q1.x * (a1.x + t1.x) + q1.y * (a1.y + t1.y)
                     + q1.z * (a1.z + t1.z) + q1.w * (a1.w + t1.w);
            p0 += __shfl_xor_sync(0xffffffffu, p0, 1);
            p0 += __shfl_xor_sync(0xffffffffu, p0, 2);
            p0 += __shfl_xor_sync(0xffffffffu, p0, 4);
            p1 += __shfl_xor_sync(0xffffffffu, p1, 1);
            p1 += __shfl_xor_sync(0xffffffffu, p1, 2);
            p1 += __shfl_xor_sync(0xffffffffu, p1, 4);
            if (wr) { aw[seg][k] = p0 * scale; aw[4 + seg][k] = p1 * scale; }
        }
    }
    __syncthreads();

    // ---- Phase 2: per-head softmax (warp w = head w) ----
    {
        float vals[7];
        float mx = -3.402823466e38f;
        #pragma unroll
        for (int i = 0; i < 7; i++) {
            const int k = l + 32 * i;
            float v = (k < LL) ? aw[w][k] : -3.402823466e38f;
            vals[i] = v;
            mx = fmaxf(mx, v);
        }
        #pragma unroll
        for (int o = 16; o > 0; o >>= 1)
            mx = fmaxf(mx, __shfl_xor_sync(0xffffffffu, mx, o));
        float s = 0.f;
        #pragma unroll
        for (int i = 0; i < 7; i++) {
            const int k = l + 32 * i;
            if (k < LL) { vals[i] = __expf(vals[i] - mx); s += vals[i]; }
        }
        #pragma unroll
        for (int o = 16; o > 0; o >>= 1)
            s += __shfl_xor_sync(0xffffffffu, s, o);
        const float inv = 1.0f / s;
        #pragma unroll
        for (int i = 0; i < 7; i++) {
            const int k = l + 32 * i;
            if (k < LL) aw[w][k] = vals[i] * inv;
        }
    }
    __syncthreads();

    // Fully-masked row: uniform softmax over ALL k -> visit every k.
    const int n3  = (nk == 0) ? LL : nk;
    const int k03 = (nk == 0) ? 0  : k0;

    // ---- Phase 3: weighted value accumulation (float4 per thread) ----
    const int j  = tid & 63;       // channel group: channels [4j, 4j+4)
    const int kq = tid >> 6;       // k offset mod 4 (uniform per warp)
    const int h3 = j >> 3;         // head of channels 4j..4j+3
    const float* __restrict__ Vs  = g_Vs + (size_t)(b * LL) * HIDD;
    const float* __restrict__ TMV = tmV + (size_t)(b * LL + q) * LL * HIDD;

    float4 acc = make_float4(0.f, 0.f, 0.f, 0.f);
    if (contig) {
        const float* __restrict__ pV = Vs  + (size_t)k03 * HIDD + 4 * j;
        const float* __restrict__ pT = TMV + (size_t)k03 * HIDD + 4 * j;
        #pragma unroll 8
        for (int i = kq; i < n3; i += 4) {
            const float wgt = aw[h3][k03 + i];
            const float4 v = *(const float4*)(pV + (size_t)i * HIDD);
            const float4 t = __ldcs((const float4*)(pT + (size_t)i * HIDD));
            acc.x += wgt * (v.x + t.x);
            acc.y += wgt * (v.y + t.y);
            acc.z += wgt * (v.z + t.z);
            acc.w += wgt * (v.w + t.w);
        }
    } else {
        #pragma unroll 4
        for (int i = kq; i < n3; i += 4) {
            const int k = klist[i];
            const float wgt = aw[h3][k];
            const float4 v = *(const float4*)(Vs + k * HIDD + 4 * j);
            const float4 t = __ldcs((const float4*)(TMV + (size_t)k * HIDD + 4 * j));
            acc.x += wgt * (v.x + t.x);
            acc.y += wgt * (v.y + t.y);
            acc.z += wgt * (v.z + t.z);
            acc.w += wgt * (v.w + t.w);
        }
    }
    red[kq][j] = acc;
    __syncthreads();
    if (kq == 0) {
        const float4 r1 = red[1][j], r2 = red[2][j], r3 = red[3][j];
        acc.x += r1.x + r2.x + r3.x;
        acc.y += r1.y + r2.y + r3.y;
        acc.z += r1.z + r2.z + r3.z;
        acc.w += r1.w + r2.w + r3.w;
        *(float4*)(out + (size_t)(b * LL + q) * HIDD + 4 * j) = acc;
    }
}

// ---------------------------------------------------------------------------
extern "C" void kernel_launch(void* const* d_in, const int* in_sizes, int n_in,
                              void* d_out, int out_size)
{
    const float* queries   = (const float*)d_in[0];
    const float* keys      = (const float*)d_in[1];
    const int*   time_mask = (const int*)  d_in[2];
    const int*   attn_mask = (const int*)  d_in[3];
    const float* tmK       = (const float*)d_in[4];
    const float* tmV       = (const float*)d_in[5];
    const float* apK       = (const float*)d_in[6];
    const float* apV       = (const float*)d_in[7];
    // d_in[8] = time_attn (unused by the forward pass)
    const float* Wq        = (const float*)d_in[9];
    const float* bq        = (const float*)d_in[10];
    const float* Wk        = (const float*)d_in[11];
    const float* bk        = (const float*)d_in[12];
    const float* Wv        = (const float*)d_in[13];
    const float* bv        = (const float*)d_in[14];
    float* out = (float*)d_out;

    dim3 pgrid(1600 / 64, HIDD / 64, 3);   // (25, 4, 3)
    proj_kernel<<<pgrid, 256>>>(queries, keys, Wq, bq, Wk, bk, Wv, bv, apK, apV);

    dim3 agrid(LL, BB);                     // (200, 8)
    attn_kernel<<<agrid, 256>>>(tmK, tmV, time_mask, attn_mask, out);
}